// round 1
// baseline (speedup 1.0000x reference)
#include <cuda_runtime.h>

// Problem constants: x is [B, C, 64, 64] -> [B, C, N]
#define BB   4
#define CC   256
#define NPIX 4096
#define KD   32     // key channels
#define OD   256    // out channels (== CC)

// Scratch (no allocations allowed — device globals are the sanctioned path)
__device__ float g_Q[BB * KD * NPIX];                 // [B, K, N]  2 MB
__device__ float g_K[BB * KD * NPIX];                 // [B, K, N]  2 MB
__device__ float g_V[BB * OD * NPIX];                 // [B, O, N] 16 MB
__device__ float g_attn[(size_t)BB * NPIX * NPIX];    // [B, N, N] 268 MB (used only if attention not in d_out)

// ---------------------------------------------------------------------------
// proj: P[b, j, n] = sum_c W[j, c] * x[b, c, n] + bias[j]
// Tile: 32 j x 64 n, loop c in 32-chunks. 256 threads, 2x4 micro-tile.
// sel: 0 -> g_Q, 1 -> g_K, 2 -> g_V
// ---------------------------------------------------------------------------
__global__ void proj_kernel(const float* __restrict__ x, const float* __restrict__ W,
                            const float* __restrict__ bias, int sel, int J) {
    float* P = (sel == 0) ? g_Q : ((sel == 1) ? g_K : g_V);
    const int b  = blockIdx.z;
    const int j0 = blockIdx.y * 32;
    const int n0 = blockIdx.x * 64;

    __shared__ float Ws[32][33];  // [cc][jj]
    __shared__ float Xs[32][68];  // [cc][nn] (pitch 68: float4-aligned, conflict-free)

    const int tid = threadIdx.x;
    const int tj = tid >> 4;      // 0..15 (j dim)
    const int tn = tid & 15;      // 0..15 (n dim)

    float acc[2][4] = {};

    for (int c0 = 0; c0 < CC; c0 += 32) {
        #pragma unroll
        for (int i = tid; i < 32 * 32; i += 256) {
            int jj = i >> 5, cc = i & 31;
            Ws[cc][jj] = W[(j0 + jj) * CC + c0 + cc];
        }
        #pragma unroll
        for (int i = tid; i < 32 * 64; i += 256) {
            int cc = i >> 6, nn = i & 63;
            Xs[cc][nn] = x[((size_t)(b * CC + c0 + cc)) * NPIX + n0 + nn];
        }
        __syncthreads();
        #pragma unroll
        for (int cc = 0; cc < 32; cc++) {
            float w0 = Ws[cc][tj * 2 + 0];
            float w1 = Ws[cc][tj * 2 + 1];
            float x0 = Xs[cc][tn * 4 + 0];
            float x1 = Xs[cc][tn * 4 + 1];
            float x2 = Xs[cc][tn * 4 + 2];
            float x3 = Xs[cc][tn * 4 + 3];
            acc[0][0] += w0 * x0; acc[0][1] += w0 * x1; acc[0][2] += w0 * x2; acc[0][3] += w0 * x3;
            acc[1][0] += w1 * x0; acc[1][1] += w1 * x1; acc[1][2] += w1 * x2; acc[1][3] += w1 * x3;
        }
        __syncthreads();
    }

    #pragma unroll
    for (int i = 0; i < 2; i++) {
        int j = j0 + tj * 2 + i;
        float bv = bias[j];
        #pragma unroll
        for (int jn = 0; jn < 4; jn++) {
            P[((size_t)(b * J + j)) * NPIX + n0 + tn * 4 + jn] = acc[i][jn] + bv;
        }
    }
}

// ---------------------------------------------------------------------------
// energy: E[b, n, m] = sum_kk Q[b, kk, n] * K[b, kk, m]
// Tile 64n x 64m, full kk=32. 256 threads, 4x4 micro-tile. float4 store.
// ---------------------------------------------------------------------------
__global__ void energy_kernel(float* __restrict__ attn_out) {
    float* E = attn_out ? attn_out : g_attn;
    const int b  = blockIdx.z;
    const int n0 = blockIdx.y * 64;
    const int m0 = blockIdx.x * 64;

    __shared__ float Qs[KD][68];
    __shared__ float Ks[KD][68];

    const int tid = threadIdx.x;
    #pragma unroll
    for (int i = tid; i < KD * 64; i += 256) {
        int kk = i >> 6, nn = i & 63;
        size_t base = ((size_t)(b * KD + kk)) * NPIX;
        Qs[kk][nn] = g_Q[base + n0 + nn];
        Ks[kk][nn] = g_K[base + m0 + nn];
    }
    __syncthreads();

    const int tq = tid >> 4;   // n dim
    const int tm = tid & 15;   // m dim
    float acc[4][4] = {};
    #pragma unroll
    for (int kk = 0; kk < KD; kk++) {
        float qv[4], kv[4];
        #pragma unroll
        for (int i = 0; i < 4; i++) qv[i] = Qs[kk][tq * 4 + i];
        #pragma unroll
        for (int j = 0; j < 4; j++) kv[j] = Ks[kk][tm * 4 + j];
        #pragma unroll
        for (int i = 0; i < 4; i++)
            #pragma unroll
            for (int j = 0; j < 4; j++) acc[i][j] += qv[i] * kv[j];
    }

    #pragma unroll
    for (int i = 0; i < 4; i++) {
        int n = n0 + tq * 4 + i;
        float4 v = make_float4(acc[i][0], acc[i][1], acc[i][2], acc[i][3]);
        *(float4*)(E + ((size_t)(b * NPIX + n)) * NPIX + m0 + tm * 4) = v;
    }
}

// ---------------------------------------------------------------------------
// softmax over last dim (length 4096), in place. One block per (b, n) row.
// ---------------------------------------------------------------------------
__global__ void softmax_kernel(float* __restrict__ attn_out) {
    float* E = attn_out ? attn_out : g_attn;
    const int b = blockIdx.y;
    const int n = blockIdx.x;
    float4* row = (float4*)(E + ((size_t)(b * NPIX + n)) * NPIX);
    const int tid = threadIdx.x;

    float4 v[4];
    float mx = -1e30f;
    #pragma unroll
    for (int i = 0; i < 4; i++) {
        v[i] = row[tid + i * 256];
        mx = fmaxf(mx, fmaxf(fmaxf(v[i].x, v[i].y), fmaxf(v[i].z, v[i].w)));
    }
    #pragma unroll
    for (int o = 16; o > 0; o >>= 1) mx = fmaxf(mx, __shfl_xor_sync(0xffffffffu, mx, o));

    __shared__ float redmax[8];
    __shared__ float redsum[8];
    if ((tid & 31) == 0) redmax[tid >> 5] = mx;
    __syncthreads();
    float bm = redmax[0];
    #pragma unroll
    for (int w = 1; w < 8; w++) bm = fmaxf(bm, redmax[w]);

    float s = 0.f;
    #pragma unroll
    for (int i = 0; i < 4; i++) {
        v[i].x = __expf(v[i].x - bm);
        v[i].y = __expf(v[i].y - bm);
        v[i].z = __expf(v[i].z - bm);
        v[i].w = __expf(v[i].w - bm);
        s += v[i].x + v[i].y + v[i].z + v[i].w;
    }
    #pragma unroll
    for (int o = 16; o > 0; o >>= 1) s += __shfl_xor_sync(0xffffffffu, s, o);
    if ((tid & 31) == 0) redsum[tid >> 5] = s;
    __syncthreads();
    float tot = 0.f;
    #pragma unroll
    for (int w = 0; w < 8; w++) tot += redsum[w];
    float inv = 1.f / tot;

    #pragma unroll
    for (int i = 0; i < 4; i++) {
        v[i].x *= inv; v[i].y *= inv; v[i].z *= inv; v[i].w *= inv;
        row[tid + i * 256] = v[i];
    }
}

// ---------------------------------------------------------------------------
// bmm + epilogue: out[b, o, m] = gamma * (sum_n V[b, o, n] * A[b, m, n]) + x[b, o, m]
// Tile 64o x 64m, loop n in 32-chunks. 256 threads, 4x4 micro-tile.
// ---------------------------------------------------------------------------
__global__ void bmm_kernel(const float* __restrict__ x, const float* __restrict__ gamma,
                           float* __restrict__ out, const float* __restrict__ attn_out) {
    const float* A = attn_out ? attn_out : g_attn;
    const int b  = blockIdx.z;
    const int o0 = blockIdx.y * 64;
    const int m0 = blockIdx.x * 64;

    __shared__ float Vs[32][68];  // [nn][oo]
    __shared__ float As[32][68];  // [nn][mm]

    const int tid = threadIdx.x;
    const int to = tid >> 4;   // o dim
    const int tm = tid & 15;   // m dim
    float acc[4][4] = {};

    for (int n0 = 0; n0 < NPIX; n0 += 32) {
        #pragma unroll
        for (int i = tid; i < 64 * 32; i += 256) {
            int oo = i >> 5, nn = i & 31;
            Vs[nn][oo] = g_V[((size_t)(b * OD + o0 + oo)) * NPIX + n0 + nn];
            As[nn][oo] = A[((size_t)(b * NPIX + m0 + oo)) * NPIX + n0 + nn];
        }
        __syncthreads();
        #pragma unroll
        for (int nn = 0; nn < 32; nn++) {
            float vv[4], av[4];
            #pragma unroll
            for (int i = 0; i < 4; i++) vv[i] = Vs[nn][to * 4 + i];
            #pragma unroll
            for (int j = 0; j < 4; j++) av[j] = As[nn][tm * 4 + j];
            #pragma unroll
            for (int i = 0; i < 4; i++)
                #pragma unroll
                for (int j = 0; j < 4; j++) acc[i][j] += vv[i] * av[j];
        }
        __syncthreads();
    }

    float g = gamma[0];
    #pragma unroll
    for (int i = 0; i < 4; i++) {
        int o = o0 + to * 4 + i;
        #pragma unroll
        for (int j = 0; j < 4; j++) {
            int m = m0 + tm * 4 + j;
            size_t idx = ((size_t)(b * OD + o)) * NPIX + m;
            out[idx] = g * acc[i][j] + x[idx];
        }
    }
}

// ---------------------------------------------------------------------------
extern "C" void kernel_launch(void* const* d_in, const int* in_sizes, int n_in,
                              void* d_out, int out_size) {
    const float* x     = (const float*)d_in[0];
    const float* Wq    = (const float*)d_in[1];
    const float* bq    = (const float*)d_in[2];
    const float* Wk    = (const float*)d_in[3];
    const float* bk    = (const float*)d_in[4];
    const float* Wv    = (const float*)d_in[5];
    const float* bv    = (const float*)d_in[6];
    const float* gamma = (const float*)d_in[7];
    float* out = (float*)d_out;

    const long long OUT_ELEMS  = (long long)BB * OD * NPIX;          // 4,194,304
    const long long ATTN_ELEMS = (long long)BB * NPIX * NPIX;        // 67,108,864

    // Reference returns (out, attention). If the harness buffer covers both,
    // write attention directly after out; otherwise keep it in device scratch.
    float* attn_out = nullptr;
    if ((long long)out_size >= OUT_ELEMS + ATTN_ELEMS)
        attn_out = out + OUT_ELEMS;

    proj_kernel<<<dim3(NPIX / 64, 1,       BB), 256>>>(x, Wq, bq, 0, KD);
    proj_kernel<<<dim3(NPIX / 64, 1,       BB), 256>>>(x, Wk, bk, 1, KD);
    proj_kernel<<<dim3(NPIX / 64, OD / 32, BB), 256>>>(x, Wv, bv, 2, OD);
    energy_kernel<<<dim3(NPIX / 64, NPIX / 64, BB), 256>>>(attn_out);
    softmax_kernel<<<dim3(NPIX, BB), 256>>>(attn_out);
    bmm_kernel<<<dim3(NPIX / 64, OD / 64, BB), 256>>>(x, gamma, out, attn_out);
}

// round 3
// speedup vs baseline: 3.5495x; 3.5495x over previous
#include <cuda_runtime.h>
#include <cuda_bf16.h>
#include <cstdint>

// Problem constants: x is [B, C, 64, 64] -> [B, C, N]
#define BB   4
#define CC   256
#define NPIX 4096
#define KD   32     // key channels
#define OD   256    // out channels (== CC)

// Scratch (no allocations allowed — device globals are the sanctioned path)
__device__ float g_Q[BB * KD * NPIX];                        // [B, K, N]  2 MB
__device__ float g_K[BB * KD * NPIX];                        // [B, K, N]  2 MB
__device__ __nv_bfloat16 g_Vh[BB * OD * NPIX];               // [B, O, N]  8 MB (bf16)
__device__ float g_attn[(size_t)BB * NPIX * NPIX];           // [B, N, N] 268 MB fp32
__device__ __nv_bfloat16 g_Ah[(size_t)BB * NPIX * NPIX];     // [B, N, N] 134 MB bf16

// ===========================================================================
// Warp MMA helpers (sm_80+ ISA — safe on the bench's plain sm_103 PTX target)
// ===========================================================================
__device__ __forceinline__ uint32_t smem_u32(const void* p) {
    uint32_t a;
    asm("{ .reg .u64 t; cvta.to.shared.u64 t, %1; cvt.u32.u64 %0, t; }" : "=r"(a) : "l"(p));
    return a;
}
__device__ __forceinline__ void ldsm_x4(uint32_t* r, uint32_t addr) {
    asm volatile("ldmatrix.sync.aligned.m8n8.x4.shared.b16 {%0,%1,%2,%3}, [%4];"
                 : "=r"(r[0]), "=r"(r[1]), "=r"(r[2]), "=r"(r[3]) : "r"(addr));
}
__device__ __forceinline__ void ldsm_x2(uint32_t* r, uint32_t addr) {
    asm volatile("ldmatrix.sync.aligned.m8n8.x2.shared.b16 {%0,%1}, [%2];"
                 : "=r"(r[0]), "=r"(r[1]) : "r"(addr));
}
__device__ __forceinline__ void mma_16816(float* c, const uint32_t* a, const uint32_t* b) {
    asm volatile(
        "mma.sync.aligned.m16n8k16.row.col.f32.bf16.bf16.f32 "
        "{%0,%1,%2,%3}, {%4,%5,%6,%7}, {%8,%9}, {%0,%1,%2,%3};"
        : "+f"(c[0]), "+f"(c[1]), "+f"(c[2]), "+f"(c[3])
        : "r"(a[0]), "r"(a[1]), "r"(a[2]), "r"(a[3]), "r"(b[0]), "r"(b[1]));
}

// ---------------------------------------------------------------------------
// proj: P[b, j, n] = sum_c W[j, c] * x[b, c, n] + bias[j]
// sel: 0 -> g_Q (fp32), 1 -> g_K (fp32), 2 -> g_Vh (bf16)
// ---------------------------------------------------------------------------
__global__ void proj_kernel(const float* __restrict__ x, const float* __restrict__ W,
                            const float* __restrict__ bias, int sel, int J) {
    const int b  = blockIdx.z;
    const int j0 = blockIdx.y * 32;
    const int n0 = blockIdx.x * 64;

    __shared__ float Ws[32][33];
    __shared__ float Xs[32][68];

    const int tid = threadIdx.x;
    const int tj = tid >> 4;
    const int tn = tid & 15;

    float acc[2][4] = {};

    for (int c0 = 0; c0 < CC; c0 += 32) {
        #pragma unroll
        for (int i = tid; i < 32 * 32; i += 256) {
            int jj = i >> 5, cc = i & 31;
            Ws[cc][jj] = W[(j0 + jj) * CC + c0 + cc];
        }
        #pragma unroll
        for (int i = tid; i < 32 * 64; i += 256) {
            int cc = i >> 6, nn = i & 63;
            Xs[cc][nn] = x[((size_t)(b * CC + c0 + cc)) * NPIX + n0 + nn];
        }
        __syncthreads();
        #pragma unroll
        for (int cc = 0; cc < 32; cc++) {
            float w0 = Ws[cc][tj * 2 + 0];
            float w1 = Ws[cc][tj * 2 + 1];
            float x0 = Xs[cc][tn * 4 + 0];
            float x1 = Xs[cc][tn * 4 + 1];
            float x2 = Xs[cc][tn * 4 + 2];
            float x3 = Xs[cc][tn * 4 + 3];
            acc[0][0] += w0 * x0; acc[0][1] += w0 * x1; acc[0][2] += w0 * x2; acc[0][3] += w0 * x3;
            acc[1][0] += w1 * x0; acc[1][1] += w1 * x1; acc[1][2] += w1 * x2; acc[1][3] += w1 * x3;
        }
        __syncthreads();
    }

    #pragma unroll
    for (int i = 0; i < 2; i++) {
        int j = j0 + tj * 2 + i;
        float bv = bias[j];
        if (sel == 2) {
            #pragma unroll
            for (int jn = 0; jn < 4; jn++)
                g_Vh[((size_t)(b * J + j)) * NPIX + n0 + tn * 4 + jn] = __float2bfloat16(acc[i][jn] + bv);
        } else {
            float* P = (sel == 0) ? g_Q : g_K;
            #pragma unroll
            for (int jn = 0; jn < 4; jn++)
                P[((size_t)(b * J + j)) * NPIX + n0 + tn * 4 + jn] = acc[i][jn] + bv;
        }
    }
}

// ---------------------------------------------------------------------------
// energy: E[b, n, m] = sum_kk Q[b, kk, n] * K[b, kk, m]
// ---------------------------------------------------------------------------
__global__ void energy_kernel(float* __restrict__ attn_out) {
    float* E = attn_out ? attn_out : g_attn;
    const int b  = blockIdx.z;
    const int n0 = blockIdx.y * 64;
    const int m0 = blockIdx.x * 64;

    __shared__ float Qs[KD][68];
    __shared__ float Ks[KD][68];

    const int tid = threadIdx.x;
    #pragma unroll
    for (int i = tid; i < KD * 64; i += 256) {
        int kk = i >> 6, nn = i & 63;
        size_t base = ((size_t)(b * KD + kk)) * NPIX;
        Qs[kk][nn] = g_Q[base + n0 + nn];
        Ks[kk][nn] = g_K[base + m0 + nn];
    }
    __syncthreads();

    const int tq = tid >> 4;
    const int tm = tid & 15;
    float acc[4][4] = {};
    #pragma unroll
    for (int kk = 0; kk < KD; kk++) {
        float qv[4], kv[4];
        #pragma unroll
        for (int i = 0; i < 4; i++) qv[i] = Qs[kk][tq * 4 + i];
        #pragma unroll
        for (int j = 0; j < 4; j++) kv[j] = Ks[kk][tm * 4 + j];
        #pragma unroll
        for (int i = 0; i < 4; i++)
            #pragma unroll
            for (int j = 0; j < 4; j++) acc[i][j] += qv[i] * kv[j];
    }

    #pragma unroll
    for (int i = 0; i < 4; i++) {
        int n = n0 + tq * 4 + i;
        float4 v = make_float4(acc[i][0], acc[i][1], acc[i][2], acc[i][3]);
        *(float4*)(E + ((size_t)(b * NPIX + n)) * NPIX + m0 + tm * 4) = v;
    }
}

// ---------------------------------------------------------------------------
// softmax over last dim (4096). Reads fp32 energy; writes bf16 copy always,
// fp32 normalized in place only when the attention output is checked.
// ---------------------------------------------------------------------------
__global__ void softmax_kernel(float* __restrict__ E, int write_fp32) {
    const int b = blockIdx.y;
    const int n = blockIdx.x;
    float4* row = (float4*)(E + ((size_t)(b * NPIX + n)) * NPIX);
    uint2* rowh = (uint2*)(g_Ah + ((size_t)(b * NPIX + n)) * NPIX);
    const int tid = threadIdx.x;

    float4 v[4];
    float mx = -1e30f;
    #pragma unroll
    for (int i = 0; i < 4; i++) {
        v[i] = row[tid + i * 256];
        mx = fmaxf(mx, fmaxf(fmaxf(v[i].x, v[i].y), fmaxf(v[i].z, v[i].w)));
    }
    #pragma unroll
    for (int o = 16; o > 0; o >>= 1) mx = fmaxf(mx, __shfl_xor_sync(0xffffffffu, mx, o));

    __shared__ float redmax[8];
    __shared__ float redsum[8];
    if ((tid & 31) == 0) redmax[tid >> 5] = mx;
    __syncthreads();
    float bm = redmax[0];
    #pragma unroll
    for (int w = 1; w < 8; w++) bm = fmaxf(bm, redmax[w]);

    float s = 0.f;
    #pragma unroll
    for (int i = 0; i < 4; i++) {
        v[i].x = __expf(v[i].x - bm);
        v[i].y = __expf(v[i].y - bm);
        v[i].z = __expf(v[i].z - bm);
        v[i].w = __expf(v[i].w - bm);
        s += v[i].x + v[i].y + v[i].z + v[i].w;
    }
    #pragma unroll
    for (int o = 16; o > 0; o >>= 1) s += __shfl_xor_sync(0xffffffffu, s, o);
    if ((tid & 31) == 0) redsum[tid >> 5] = s;
    __syncthreads();
    float tot = 0.f;
    #pragma unroll
    for (int w = 0; w < 8; w++) tot += redsum[w];
    float inv = 1.f / tot;

    #pragma unroll
    for (int i = 0; i < 4; i++) {
        v[i].x *= inv; v[i].y *= inv; v[i].z *= inv; v[i].w *= inv;
        __nv_bfloat162 p0 = __float22bfloat162_rn(make_float2(v[i].x, v[i].y));
        __nv_bfloat162 p1 = __float22bfloat162_rn(make_float2(v[i].z, v[i].w));
        uint2 packed;
        packed.x = *(uint32_t*)&p0;
        packed.y = *(uint32_t*)&p1;
        rowh[tid + i * 256] = packed;
        if (write_fp32) row[tid + i * 256] = v[i];
    }
}

// ---------------------------------------------------------------------------
// bmm via mma.sync (HMMA bf16):
//   out[b, o, m] = gamma * (sum_n Vh[b, o, n] * Ah[b, m, n]) + x[b, o, m]
// Per-batch GEMM: M=256 (o), N=4096 (m), K=4096 (n); both operands K-contiguous
// -> mma row.col form directly. CTA tile 128x128, 8 warps of 64x32.
// K-chunks of 32, double-buffered smem with 80B padded rows (conflict-free ldmatrix).
// ---------------------------------------------------------------------------
#define BMM_THREADS 256
#define KC 32
#define NKC (NPIX / KC)            // 128
#define ROWB 80                    // padded row pitch in bytes (32 bf16 = 64B data)
#define TILE_B (128 * ROWB)        // 10240
#define BUF_B (2 * TILE_B)         // V tile + A tile

__global__ void __launch_bounds__(BMM_THREADS, 2)
bmm_mma_kernel(const float* __restrict__ x, const float* __restrict__ gamma,
               float* __restrict__ out) {
    __shared__ __align__(16) char smem[2 * BUF_B];   // 40 KB

    const int tid  = threadIdx.x;
    const int wid  = tid >> 5;
    const int lane = tid & 31;
    const int m0 = blockIdx.x * 128;   // attention pixel tile
    const int o0 = blockIdx.y * 128;   // out-channel tile
    const int b  = blockIdx.z;

    const int wm = (wid & 1) * 64;     // warp M offset (o)
    const int wn = (wid >> 1) * 32;    // warp N offset (m)

    const uint32_t sbase = smem_u32(smem);

    float acc[4][4][4];
    #pragma unroll
    for (int i = 0; i < 4; i++)
        #pragma unroll
        for (int j = 0; j < 4; j++)
            #pragma unroll
            for (int k = 0; k < 4; k++) acc[i][j][k] = 0.f;

    // per-thread load slots: idx = tid + k*256, k=0..3 over [0,1024)
    // idx -> tile t = idx>>9 (0: V, 1: attn), row r = (idx>>2)&127, col c = idx&3
    const __nv_bfloat16* srcs[4];
    uint32_t dsts[4];
    #pragma unroll
    for (int k = 0; k < 4; k++) {
        int idx = tid + k * 256;
        int t = idx >> 9;
        int r = (idx >> 2) & 127;
        int c = idx & 3;
        if (t == 0)
            srcs[k] = g_Vh + ((size_t)(b * OD + o0 + r)) * NPIX + c * 8;
        else
            srcs[k] = g_Ah + ((size_t)b * NPIX + m0 + r) * NPIX + c * 8;
        dsts[k] = sbase + t * TILE_B + r * ROWB + c * 16;
    }

    // prime buffer 0
    #pragma unroll
    for (int k = 0; k < 4; k++) {
        uint4 v = *(const uint4*)(srcs[k]);
        *(uint4*)(size_t)0;  // (no-op placeholder removed by compiler? avoid) 
        asm volatile("st.shared.v4.b32 [%0], {%1,%2,%3,%4};" ::
                     "r"(dsts[k]), "r"(v.x), "r"(v.y), "r"(v.z), "r"(v.w) : "memory");
    }
    __syncthreads();

    for (int kc = 0; kc < NKC; kc++) {
        // prefetch next chunk into registers
        uint4 pf[4];
        const bool more = (kc + 1 < NKC);
        if (more) {
            #pragma unroll
            for (int k = 0; k < 4; k++)
                pf[k] = *(const uint4*)(srcs[k] + (size_t)(kc + 1) * KC);
        }

        // compute on buffer kc&1
        const uint32_t vb = sbase + (kc & 1) * BUF_B;            // V tile
        const uint32_t ab = vb + TILE_B;                          // attn tile
        #pragma unroll
        for (int ks = 0; ks < 2; ks++) {
            uint32_t afr[4][4];
            #pragma unroll
            for (int mt = 0; mt < 4; mt++) {
                uint32_t addr = vb + (uint32_t)((wm + mt * 16 + (lane & 15)) * ROWB
                                                + ks * 32 + (lane >> 4) * 16);
                ldsm_x4(afr[mt], addr);
            }
            uint32_t bfr[4][2];
            #pragma unroll
            for (int nt = 0; nt < 4; nt++) {
                uint32_t addr = ab + (uint32_t)((wn + nt * 8 + (lane & 7)) * ROWB
                                                + ks * 32 + ((lane >> 3) & 1) * 16);
                ldsm_x2(bfr[nt], addr);
            }
            #pragma unroll
            for (int mt = 0; mt < 4; mt++)
                #pragma unroll
                for (int nt = 0; nt < 4; nt++)
                    mma_16816(acc[mt][nt], afr[mt], bfr[nt]);
        }

        // store prefetched chunk into the other buffer
        if (more) {
            const uint32_t off = ((kc + 1) & 1) * BUF_B;
            #pragma unroll
            for (int k = 0; k < 4; k++)
                asm volatile("st.shared.v4.b32 [%0], {%1,%2,%3,%4};" ::
                             "r"(dsts[k] + off), "r"(pf[k].x), "r"(pf[k].y),
                             "r"(pf[k].z), "r"(pf[k].w) : "memory");
        }
        __syncthreads();
    }

    // ---- epilogue: out = gamma * acc + x ----
    const float g = gamma[0];
    #pragma unroll
    for (int mt = 0; mt < 4; mt++) {
        #pragma unroll
        for (int nt = 0; nt < 4; nt++) {
            int row0 = o0 + wm + mt * 16 + (lane >> 2);
            int col  = m0 + wn + nt * 8 + (lane & 3) * 2;
            size_t i0 = ((size_t)(b * OD + row0)) * NPIX + col;
            size_t i1 = i0 + (size_t)8 * NPIX;   // row0 + 8
            float2 x0 = *(const float2*)(x + i0);
            float2 x1 = *(const float2*)(x + i1);
            float2 o0v, o1v;
            o0v.x = g * acc[mt][nt][0] + x0.x;
            o0v.y = g * acc[mt][nt][1] + x0.y;
            o1v.x = g * acc[mt][nt][2] + x1.x;
            o1v.y = g * acc[mt][nt][3] + x1.y;
            *(float2*)(out + i0) = o0v;
            *(float2*)(out + i1) = o1v;
        }
    }
}

// ---------------------------------------------------------------------------
extern "C" void kernel_launch(void* const* d_in, const int* in_sizes, int n_in,
                              void* d_out, int out_size) {
    const float* x     = (const float*)d_in[0];
    const float* Wq    = (const float*)d_in[1];
    const float* bq    = (const float*)d_in[2];
    const float* Wk    = (const float*)d_in[3];
    const float* bk    = (const float*)d_in[4];
    const float* Wv    = (const float*)d_in[5];
    const float* bv    = (const float*)d_in[6];
    const float* gamma = (const float*)d_in[7];
    float* out = (float*)d_out;

    const long long OUT_ELEMS  = (long long)BB * OD * NPIX;
    const long long ATTN_ELEMS = (long long)BB * NPIX * NPIX;

    float* attn_out = nullptr;
    if ((long long)out_size >= OUT_ELEMS + ATTN_ELEMS)
        attn_out = out + OUT_ELEMS;

    proj_kernel<<<dim3(NPIX / 64, 1,       BB), 256>>>(x, Wq, bq, 0, KD);
    proj_kernel<<<dim3(NPIX / 64, 1,       BB), 256>>>(x, Wk, bk, 1, KD);
    proj_kernel<<<dim3(NPIX / 64, OD / 32, BB), 256>>>(x, Wv, bv, 2, OD);
    energy_kernel<<<dim3(NPIX / 64, NPIX / 64, BB), 256>>>(attn_out);
    {
        float* E = attn_out ? attn_out : g_attn;
        softmax_kernel<<<dim3(NPIX, BB), 256>>>(E, attn_out ? 1 : 0);
    }
    bmm_mma_kernel<<<dim3(NPIX / 128, OD / 128, BB), BMM_THREADS>>>(x, gamma, out);
}

// round 5
// speedup vs baseline: 4.0151x; 1.1312x over previous
#include <cuda_runtime.h>
#include <cuda_bf16.h>
#include <cstdint>

// Problem constants: x is [B, C, 64, 64] -> [B, C, N]
#define BB   4
#define CC   256
#define NPIX 4096
#define KD   32     // key channels
#define OD   256    // out channels (== CC)

// Scratch (no allocations allowed — device globals are the sanctioned path)
// Q/K stored as bf16 hi|lo split pairs, pixel-major: [b][n][0:32]=hi, [32:64]=lo
__device__ __nv_bfloat16 g_Qs[BB * NPIX * 64];               // 4 MB
__device__ __nv_bfloat16 g_Ks[BB * NPIX * 64];               // 4 MB
__device__ __nv_bfloat16 g_Vh[BB * OD * NPIX];               // [B, O, N]  8 MB (bf16)
__device__ float g_attn[(size_t)BB * NPIX * NPIX];           // [B, N, N] 268 MB fp32
__device__ __nv_bfloat16 g_Ah[(size_t)BB * NPIX * NPIX];     // [B, N, N] 134 MB bf16

// ===========================================================================
// Warp MMA helpers (sm_80+ ISA — safe on the bench's plain sm_103 PTX target)
// ===========================================================================
__device__ __forceinline__ uint32_t smem_u32(const void* p) {
    uint32_t a;
    asm("{ .reg .u64 t; cvta.to.shared.u64 t, %1; cvt.u32.u64 %0, t; }" : "=r"(a) : "l"(p));
    return a;
}
__device__ __forceinline__ void ldsm_x4(uint32_t* r, uint32_t addr) {
    asm volatile("ldmatrix.sync.aligned.m8n8.x4.shared.b16 {%0,%1,%2,%3}, [%4];"
                 : "=r"(r[0]), "=r"(r[1]), "=r"(r[2]), "=r"(r[3]) : "r"(addr));
}
__device__ __forceinline__ void ldsm_x2(uint32_t* r, uint32_t addr) {
    asm volatile("ldmatrix.sync.aligned.m8n8.x2.shared.b16 {%0,%1}, [%2];"
                 : "=r"(r[0]), "=r"(r[1]) : "r"(addr));
}
__device__ __forceinline__ void mma_16816(float* c, const uint32_t* a, const uint32_t* b) {
    asm volatile(
        "mma.sync.aligned.m16n8k16.row.col.f32.bf16.bf16.f32 "
        "{%0,%1,%2,%3}, {%4,%5,%6,%7}, {%8,%9}, {%0,%1,%2,%3};"
        : "+f"(c[0]), "+f"(c[1]), "+f"(c[2]), "+f"(c[3])
        : "r"(a[0]), "r"(a[1]), "r"(a[2]), "r"(a[3]), "r"(b[0]), "r"(b[1]));
}

// ---------------------------------------------------------------------------
// proj: P[b, j, n] = sum_c W[j, c] * x[b, c, n] + bias[j]
// sel 0/1 -> g_Qs/g_Ks as bf16 hi|lo split, [b][n][64] layout
// sel 2   -> g_Vh bf16, [b][o][n] layout
// ---------------------------------------------------------------------------
__global__ void proj_kernel(const float* __restrict__ x, const float* __restrict__ W,
                            const float* __restrict__ bias, int sel, int J) {
    const int b  = blockIdx.z;
    const int j0 = blockIdx.y * 32;
    const int n0 = blockIdx.x * 64;

    __shared__ float Ws[32][33];
    __shared__ float Xs[32][68];

    const int tid = threadIdx.x;
    const int tj = tid >> 4;
    const int tn = tid & 15;

    float acc[2][4] = {};

    for (int c0 = 0; c0 < CC; c0 += 32) {
        #pragma unroll
        for (int i = tid; i < 32 * 32; i += 256) {
            int jj = i >> 5, cc = i & 31;
            Ws[cc][jj] = W[(j0 + jj) * CC + c0 + cc];
        }
        #pragma unroll
        for (int i = tid; i < 32 * 64; i += 256) {
            int cc = i >> 6, nn = i & 63;
            Xs[cc][nn] = x[((size_t)(b * CC + c0 + cc)) * NPIX + n0 + nn];
        }
        __syncthreads();
        #pragma unroll
        for (int cc = 0; cc < 32; cc++) {
            float w0 = Ws[cc][tj * 2 + 0];
            float w1 = Ws[cc][tj * 2 + 1];
            float x0 = Xs[cc][tn * 4 + 0];
            float x1 = Xs[cc][tn * 4 + 1];
            float x2 = Xs[cc][tn * 4 + 2];
            float x3 = Xs[cc][tn * 4 + 3];
            acc[0][0] += w0 * x0; acc[0][1] += w0 * x1; acc[0][2] += w0 * x2; acc[0][3] += w0 * x3;
            acc[1][0] += w1 * x0; acc[1][1] += w1 * x1; acc[1][2] += w1 * x2; acc[1][3] += w1 * x3;
        }
        __syncthreads();
    }

    if (sel == 2) {
        #pragma unroll
        for (int i = 0; i < 2; i++) {
            int j = j0 + tj * 2 + i;
            float bv = bias[j];
            #pragma unroll
            for (int jn = 0; jn < 4; jn++)
                g_Vh[((size_t)(b * J + j)) * NPIX + n0 + tn * 4 + jn] = __float2bfloat16(acc[i][jn] + bv);
        }
    } else {
        // stage j x n tile in smem (reuse Xs), then write transposed hi|lo rows
        #pragma unroll
        for (int i = 0; i < 2; i++) {
            int j = tj * 2 + i;
            float bv = bias[j0 + j];
            #pragma unroll
            for (int jn = 0; jn < 4; jn++)
                Xs[j][tn * 4 + jn] = acc[i][jn] + bv;   // Xs[j][n]
        }
        __syncthreads();
        __nv_bfloat16* P = (sel == 0) ? g_Qs : g_Ks;
        // one (n, j-group-of-8) per thread: 64 n x 4 groups = 256
        int n = tid >> 2;
        int g = tid & 3;
        __nv_bfloat16 hi[8], lo[8];
        #pragma unroll
        for (int jj = 0; jj < 8; jj++) {
            float v = Xs[g * 8 + jj][n];
            hi[jj] = __float2bfloat16(v);
            lo[jj] = __float2bfloat16(v - __bfloat162float(hi[jj]));
        }
        __nv_bfloat16* dst = P + ((size_t)(b * NPIX + n0 + n)) * 64;
        *(uint4*)(dst + g * 8)      = *(uint4*)hi;
        *(uint4*)(dst + 32 + g * 8) = *(uint4*)lo;
    }
}

// ---------------------------------------------------------------------------
// energy via HMMA with 3-term bf16 split (near-fp32):
//   E[b, n, m] = sum_k Q[b,n,k] * K[b,m,k],  Q/K given as hi|lo bf16 pairs.
// CTA tile 128n x 128m, 8 warps of 64n x 32m, single K=32 panel in smem.
// smem pitch 144 B = 9*16: 16B-aligned stores/ldsm, and rows step 4 banks
// (4r mod 32 distinct for r=0..7) -> conflict-free ldmatrix.
// ---------------------------------------------------------------------------
#define EN_PITCH 144
#define EN_TILE (128 * EN_PITCH)

__global__ void __launch_bounds__(256)
energy_mma_kernel(float* __restrict__ attn_out) {
    float* E = attn_out ? attn_out : g_attn;
    __shared__ __align__(16) char esm[2 * EN_TILE];   // Q tile, K tile (36864 B)

    const int tid  = threadIdx.x;
    const int wid  = tid >> 5;
    const int lane = tid & 31;
    const int m0 = blockIdx.x * 128;
    const int n0 = blockIdx.y * 128;
    const int b  = blockIdx.z;

    const uint32_t sbase = smem_u32(esm);

    // load both tiles: 2 tensors x 128 rows x 128B (hi|lo) = 2048 x 16B
    #pragma unroll
    for (int i = tid; i < 2048; i += 256) {
        int t = i >> 10;            // 0 = Q, 1 = K
        int r = (i >> 3) & 127;
        int c = i & 7;
        const __nv_bfloat16* src =
            (t ? g_Ks : g_Qs) + ((size_t)(b * NPIX + (t ? m0 : n0) + r)) * 64 + c * 8;
        uint4 v = *(const uint4*)src;
        asm volatile("st.shared.v4.b32 [%0], {%1,%2,%3,%4};" ::
                     "r"(sbase + t * EN_TILE + r * EN_PITCH + c * 16),
                     "r"(v.x), "r"(v.y), "r"(v.z), "r"(v.w) : "memory");
    }
    __syncthreads();

    const int wm = (wid & 1) * 64;     // n offset
    const int wn = (wid >> 1) * 32;    // m offset
    const uint32_t qb = sbase;
    const uint32_t kb = sbase + EN_TILE;

    float acc[4][4][4];
    #pragma unroll
    for (int i = 0; i < 4; i++)
        #pragma unroll
        for (int j = 0; j < 4; j++)
            #pragma unroll
            for (int k = 0; k < 4; k++) acc[i][j][k] = 0.f;

    #pragma unroll
    for (int ks = 0; ks < 2; ks++) {
        uint32_t bhi[4][2], blo[4][2];
        #pragma unroll
        for (int nt = 0; nt < 4; nt++) {
            uint32_t addr = kb + (uint32_t)((wn + nt * 8 + (lane & 7)) * EN_PITCH
                                            + ks * 32 + ((lane >> 3) & 1) * 16);
            ldsm_x2(bhi[nt], addr);
            ldsm_x2(blo[nt], addr + 64);
        }
        #pragma unroll
        for (int mt = 0; mt < 4; mt++) {
            uint32_t ahi[4], alo[4];
            uint32_t addr = qb + (uint32_t)((wm + mt * 16 + (lane & 15)) * EN_PITCH
                                            + ks * 32 + (lane >> 4) * 16);
            ldsm_x4(ahi, addr);
            ldsm_x4(alo, addr + 64);
            #pragma unroll
            for (int nt = 0; nt < 4; nt++) {
                mma_16816(acc[mt][nt], ahi, bhi[nt]);   // hi*hi
                mma_16816(acc[mt][nt], ahi, blo[nt]);   // hi*lo
                mma_16816(acc[mt][nt], alo, bhi[nt]);   // lo*hi
            }
        }
    }

    #pragma unroll
    for (int mt = 0; mt < 4; mt++) {
        #pragma unroll
        for (int nt = 0; nt < 4; nt++) {
            int row = n0 + wm + mt * 16 + (lane >> 2);
            int col = m0 + wn + nt * 8 + (lane & 3) * 2;
            size_t i0 = ((size_t)(b * NPIX + row)) * NPIX + col;
            *(float2*)(E + i0)                      = make_float2(acc[mt][nt][0], acc[mt][nt][1]);
            *(float2*)(E + i0 + (size_t)8 * NPIX)   = make_float2(acc[mt][nt][2], acc[mt][nt][3]);
        }
    }
}

// ---------------------------------------------------------------------------
// softmax over last dim (4096). Reads fp32 energy; writes bf16 copy always,
// fp32 normalized in place only when the attention output is checked.
// ---------------------------------------------------------------------------
__global__ void softmax_kernel(float* __restrict__ E, int write_fp32) {
    const int b = blockIdx.y;
    const int n = blockIdx.x;
    float4* row = (float4*)(E + ((size_t)(b * NPIX + n)) * NPIX);
    uint2* rowh = (uint2*)(g_Ah + ((size_t)(b * NPIX + n)) * NPIX);
    const int tid = threadIdx.x;

    float4 v[4];
    float mx = -1e30f;
    #pragma unroll
    for (int i = 0; i < 4; i++) {
        v[i] = row[tid + i * 256];
        mx = fmaxf(mx, fmaxf(fmaxf(v[i].x, v[i].y), fmaxf(v[i].z, v[i].w)));
    }
    #pragma unroll
    for (int o = 16; o > 0; o >>= 1) mx = fmaxf(mx, __shfl_xor_sync(0xffffffffu, mx, o));

    __shared__ float redmax[8];
    __shared__ float redsum[8];
    if ((tid & 31) == 0) redmax[tid >> 5] = mx;
    __syncthreads();
    float bm = redmax[0];
    #pragma unroll
    for (int w = 1; w < 8; w++) bm = fmaxf(bm, redmax[w]);

    float s = 0.f;
    #pragma unroll
    for (int i = 0; i < 4; i++) {
        v[i].x = __expf(v[i].x - bm);
        v[i].y = __expf(v[i].y - bm);
        v[i].z = __expf(v[i].z - bm);
        v[i].w = __expf(v[i].w - bm);
        s += v[i].x + v[i].y + v[i].z + v[i].w;
    }
    #pragma unroll
    for (int o = 16; o > 0; o >>= 1) s += __shfl_xor_sync(0xffffffffu, s, o);
    if ((tid & 31) == 0) redsum[tid >> 5] = s;
    __syncthreads();
    float tot = 0.f;
    #pragma unroll
    for (int w = 0; w < 8; w++) tot += redsum[w];
    float inv = 1.f / tot;

    #pragma unroll
    for (int i = 0; i < 4; i++) {
        v[i].x *= inv; v[i].y *= inv; v[i].z *= inv; v[i].w *= inv;
        __nv_bfloat162 p0 = __float22bfloat162_rn(make_float2(v[i].x, v[i].y));
        __nv_bfloat162 p1 = __float22bfloat162_rn(make_float2(v[i].z, v[i].w));
        uint2 packed;
        packed.x = *(uint32_t*)&p0;
        packed.y = *(uint32_t*)&p1;
        rowh[tid + i * 256] = packed;
        if (write_fp32) row[tid + i * 256] = v[i];
    }
}

// ---------------------------------------------------------------------------
// bmm via mma.sync (HMMA bf16):
//   out[b, o, m] = gamma * (sum_n Vh[b, o, n] * Ah[b, m, n]) + x[b, o, m]
// CTA tile 128x128, 8 warps of 64x32. K-chunks of 32, double-buffered smem,
// 80B padded rows (conflict-free ldmatrix), register prefetch.
// ---------------------------------------------------------------------------
#define BMM_THREADS 256
#define KC 32
#define NKC (NPIX / KC)            // 128
#define ROWB 80                    // padded row pitch in bytes (32 bf16 = 64B data)
#define TILE_B (128 * ROWB)        // 10240
#define BUF_B (2 * TILE_B)         // V tile + A tile

__global__ void __launch_bounds__(BMM_THREADS, 2)
bmm_mma_kernel(const float* __restrict__ x, const float* __restrict__ gamma,
               float* __restrict__ out) {
    __shared__ __align__(16) char smem[2 * BUF_B];   // 40 KB

    const int tid  = threadIdx.x;
    const int wid  = tid >> 5;
    const int lane = tid & 31;
    const int m0 = blockIdx.x * 128;   // attention pixel tile
    const int o0 = blockIdx.y * 128;   // out-channel tile
    const int b  = blockIdx.z;

    const int wm = (wid & 1) * 64;     // warp M offset (o)
    const int wn = (wid >> 1) * 32;    // warp N offset (m)

    const uint32_t sbase = smem_u32(smem);

    float acc[4][4][4];
    #pragma unroll
    for (int i = 0; i < 4; i++)
        #pragma unroll
        for (int j = 0; j < 4; j++)
            #pragma unroll
            for (int k = 0; k < 4; k++) acc[i][j][k] = 0.f;

    const __nv_bfloat16* srcs[4];
    uint32_t dsts[4];
    #pragma unroll
    for (int k = 0; k < 4; k++) {
        int idx = tid + k * 256;
        int t = idx >> 9;
        int r = (idx >> 2) & 127;
        int c = idx & 3;
        if (t == 0)
            srcs[k] = g_Vh + ((size_t)(b * OD + o0 + r)) * NPIX + c * 8;
        else
            srcs[k] = g_Ah + ((size_t)b * NPIX + m0 + r) * NPIX + c * 8;
        dsts[k] = sbase + t * TILE_B + r * ROWB + c * 16;
    }

    // prime buffer 0
    #pragma unroll
    for (int k = 0; k < 4; k++) {
        uint4 v = *(const uint4*)(srcs[k]);
        asm volatile("st.shared.v4.b32 [%0], {%1,%2,%3,%4};" ::
                     "r"(dsts[k]), "r"(v.x), "r"(v.y), "r"(v.z), "r"(v.w) : "memory");
    }
    __syncthreads();

    for (int kc = 0; kc < NKC; kc++) {
        uint4 pf[4];
        const bool more = (kc + 1 < NKC);
        if (more) {
            #pragma unroll
            for (int k = 0; k < 4; k++)
                pf[k] = *(const uint4*)(srcs[k] + (size_t)(kc + 1) * KC);
        }

        const uint32_t vb = sbase + (kc & 1) * BUF_B;
        const uint32_t ab = vb + TILE_B;
        #pragma unroll
        for (int ks = 0; ks < 2; ks++) {
            uint32_t afr[4][4];
            #pragma unroll
            for (int mt = 0; mt < 4; mt++) {
                uint32_t addr = vb + (uint32_t)((wm + mt * 16 + (lane & 15)) * ROWB
                                                + ks * 32 + (lane >> 4) * 16);
                ldsm_x4(afr[mt], addr);
            }
            uint32_t bfr[4][2];
            #pragma unroll
            for (int nt = 0; nt < 4; nt++) {
                uint32_t addr = ab + (uint32_t)((wn + nt * 8 + (lane & 7)) * ROWB
                                                + ks * 32 + ((lane >> 3) & 1) * 16);
                ldsm_x2(bfr[nt], addr);
            }
            #pragma unroll
            for (int mt = 0; mt < 4; mt++)
                #pragma unroll
                for (int nt = 0; nt < 4; nt++)
                    mma_16816(acc[mt][nt], afr[mt], bfr[nt]);
        }

        if (more) {
            const uint32_t off = ((kc + 1) & 1) * BUF_B;
            #pragma unroll
            for (int k = 0; k < 4; k++)
                asm volatile("st.shared.v4.b32 [%0], {%1,%2,%3,%4};" ::
                             "r"(dsts[k] + off), "r"(pf[k].x), "r"(pf[k].y),
                             "r"(pf[k].z), "r"(pf[k].w) : "memory");
        }
        __syncthreads();
    }

    const float g = gamma[0];
    #pragma unroll
    for (int mt = 0; mt < 4; mt++) {
        #pragma unroll
        for (int nt = 0; nt < 4; nt++) {
            int row0 = o0 + wm + mt * 16 + (lane >> 2);
            int col  = m0 + wn + nt * 8 + (lane & 3) * 2;
            size_t i0 = ((size_t)(b * OD + row0)) * NPIX + col;
            size_t i1 = i0 + (size_t)8 * NPIX;
            float2 x0 = *(const float2*)(x + i0);
            float2 x1 = *(const float2*)(x + i1);
            float2 o0v, o1v;
            o0v.x = g * acc[mt][nt][0] + x0.x;
            o0v.y = g * acc[mt][nt][1] + x0.y;
            o1v.x = g * acc[mt][nt][2] + x1.x;
            o1v.y = g * acc[mt][nt][3] + x1.y;
            *(float2*)(out + i0) = o0v;
            *(float2*)(out + i1) = o1v;
        }
    }
}

// ---------------------------------------------------------------------------
extern "C" void kernel_launch(void* const* d_in, const int* in_sizes, int n_in,
                              void* d_out, int out_size) {
    const float* x     = (const float*)d_in[0];
    const float* Wq    = (const float*)d_in[1];
    const float* bq    = (const float*)d_in[2];
    const float* Wk    = (const float*)d_in[3];
    const float* bk    = (const float*)d_in[4];
    const float* Wv    = (const float*)d_in[5];
    const float* bv    = (const float*)d_in[6];
    const float* gamma = (const float*)d_in[7];
    float* out = (float*)d_out;

    const long long OUT_ELEMS  = (long long)BB * OD * NPIX;
    const long long ATTN_ELEMS = (long long)BB * NPIX * NPIX;

    float* attn_out = nullptr;
    if ((long long)out_size >= OUT_ELEMS + ATTN_ELEMS)
        attn_out = out + OUT_ELEMS;

    proj_kernel<<<dim3(NPIX / 64, 1,       BB), 256>>>(x, Wq, bq, 0, KD);
    proj_kernel<<<dim3(NPIX / 64, 1,       BB), 256>>>(x, Wk, bk, 1, KD);
    proj_kernel<<<dim3(NPIX / 64, OD / 32, BB), 256>>>(x, Wv, bv, 2, OD);
    energy_mma_kernel<<<dim3(NPIX / 128, NPIX / 128, BB), 256>>>(attn_out);
    {
        float* E = attn_out ? attn_out : g_attn;
        softmax_kernel<<<dim3(NPIX, BB), 256>>>(E, attn_out ? 1 : 0);
    }
    bmm_mma_kernel<<<dim3(NPIX / 128, OD / 128, BB), BMM_THREADS>>>(x, gamma, out);
}